// round 14
// baseline (speedup 1.0000x reference)
#include <cuda_runtime.h>
#include <cuda_bf16.h>
#include <cstdint>

// ---------------- problem constants ----------------
#define NS      512
#define KSEG    16
#define SEGD    8192
#define FSTRIDE (KSEG * SEGD)
#define TEMP_INV (1.0f / 0.7f)        // applied once in epilogue (exact fold)
#define NCLASS  10

// ---------------- GEMM config ----------------
#define MT      64                     // class tile
#define CK      64                     // K elems per chunk (bf16 row = 128B)
#define KSPLIT  8
#define KQ      (SEGD / KSPLIT)        // 1024
#define CHPU    (KQ / CK)              // 16 chunks per unit
#define OP_BYTES (MT * 128)            // 8192 per operand buffer
// smem: A double buf 16 KB + B double buf 16 KB = 32 KB static

#define NROWPAD 640
#define MAXP    32
#define NPL     (KSEG * KSPLIT)        // 128 gram planes

// ---------------- device scratch ----------------
__device__ float g_gram[(size_t)NPL * MAXP * MT * MT];  // 64 MB partials
__device__ float g_partials[2048];
__device__ int   g_red_count;
// schedule (rebuilt by prep every launch; deterministic)
__device__ int   g_rowsrc[NROWPAD];    // grouped row -> original sample (pad->0)
__device__ int   g_cnum[NCLASS], g_cT[NCLASS], g_cpbase[NCLASS];
__device__ int   g_pairM[MAXP], g_pairN[MAXP];
__device__ int   g_P;

// ---------------- helpers ----------------
__device__ __forceinline__ uint32_t smem_u32(const void* p) {
    uint32_t a;
    asm("{ .reg .u64 t; cvta.to.shared.u64 t, %1; cvt.u32.u64 %0, t; }" : "=r"(a) : "l"(p));
    return a;
}
#define SW128(o) ((o) ^ (((o) >> 3) & 0x70))

__device__ __forceinline__ void ldsm_x4(uint32_t& r0, uint32_t& r1, uint32_t& r2, uint32_t& r3,
                                        uint32_t addr) {
    asm volatile("ldmatrix.sync.aligned.m8n8.x4.shared.b16 {%0,%1,%2,%3}, [%4];"
                 : "=r"(r0), "=r"(r1), "=r"(r2), "=r"(r3) : "r"(addr));
}
__device__ __forceinline__ void mma16816(float* c, const uint32_t* a, uint32_t b0, uint32_t b1) {
    asm volatile(
        "mma.sync.aligned.m16n8k16.row.col.f32.bf16.bf16.f32 "
        "{%0,%1,%2,%3}, {%4,%5,%6,%7}, {%8,%9}, {%0,%1,%2,%3};"
        : "+f"(c[0]), "+f"(c[1]), "+f"(c[2]), "+f"(c[3])
        : "r"(a[0]), "r"(a[1]), "r"(a[2]), "r"(a[3]), "r"(b0), "r"(b1));
}
// 8 raw f32 -> uint4 of bf16x2 (k-consecutive pairs, lo = first)
__device__ __forceinline__ uint4 cvt8(const float4& a, const float4& b) {
    __nv_bfloat162 h0 = __floats2bfloat162_rn(a.x, a.y);
    __nv_bfloat162 h1 = __floats2bfloat162_rn(a.z, a.w);
    __nv_bfloat162 h2 = __floats2bfloat162_rn(b.x, b.y);
    __nv_bfloat162 h3 = __floats2bfloat162_rn(b.z, b.w);
    uint4 v;
    v.x = *(uint32_t*)&h0; v.y = *(uint32_t*)&h1;
    v.z = *(uint32_t*)&h2; v.w = *(uint32_t*)&h3;
    return v;
}

// ---------------------------------------------------------------------------
// Prep (1 block, 512 threads): label dtype detect; stable grouping rank via
// __match_any_sync + per-warp class histograms; tile-pair schedule.
// ---------------------------------------------------------------------------
__global__ void prep_kernel(const int* __restrict__ lab) {
    __shared__ int wcnt[16][NCLASS];
    __shared__ int cnt[NCLASS], cstart[NCLASS];
    const int t = threadIdx.x;
    const int lane = t & 31, w = t >> 5;

    // int32 vs int64: labels 0..9 -> odd 32-bit words all zero iff int64
    int viol = (lab[2 * t + 1] != 0) ? 1 : 0;
    int is32 = __syncthreads_or(viol);
    const int v = is32 ? lab[t] : lab[2 * t];

    if (t < 16 * NCLASS) ((int*)wcnt)[t] = 0;
    g_rowsrc[t] = 0;
    if (t < NROWPAD - NS) g_rowsrc[NS + t] = 0;
    __syncthreads();

    const unsigned m = __match_any_sync(0xffffffffu, v);
    const int riw = __popc(m & ((1u << lane) - 1));
    if (lane == (__ffs(m) - 1)) wcnt[w][v] = __popc(m);
    __syncthreads();

    int rank = riw;
    for (int ww = 0; ww < w; ww++) rank += wcnt[ww][v];

    if (t < NCLASS) {
        int s = 0;
        for (int ww = 0; ww < 16; ww++) s += wcnt[ww][t];
        cnt[t] = s;
    }
    __syncthreads();

    if (t == 0) {
        int start = 0, P = 0;
        for (int c = 0; c < NCLASS; c++) {
            const int n = cnt[c];
            cstart[c] = start;
            g_cnum[c] = n;
            const int T = (n + MT - 1) / MT;
            g_cT[c] = T;
            g_cpbase[c] = P;
            for (int ti = 0; ti < T; ti++)
                for (int tj = ti; tj < T; tj++) {
                    if (P < MAXP) { g_pairM[P] = start + MT * ti; g_pairN[P] = start + MT * tj; }
                    P++;
                }
            start += n;
        }
        g_P = (P > MAXP) ? MAXP : P;
    }
    __syncthreads();
    g_rowsrc[cstart[v] + rank] = t;
}

// ---------------------------------------------------------------------------
// One-pass block-diagonal Gram GEMM: LDG f32 -> registers -> cvt bf16 -> STS
// (double-buffered 8KB tiles) -> ldmatrix/MMA (R10's proven fragment path).
// f32 never touches smem; features read from HBM exactly once.
// Grid (MAXP, KSEG, KSPLIT); pidx >= g_P exits. 128 threads, 2x2 warp grid
// of 32x32 tiles over a 64x64 class tile. One __syncthreads per chunk.
// Diagonal pairs (the common case) skip the B tile entirely (B == A).
// ---------------------------------------------------------------------------
__global__ void __launch_bounds__(128, 4)
gemm_kernel(const float* __restrict__ F) {
    const int pidx = blockIdx.x;
    if (pidx >= g_P) return;
    const int seg = blockIdx.y;
    const int kq  = blockIdx.z;

    __shared__ __align__(1024) char smem[4 * OP_BYTES];  // A0 A1 B0 B1 = 32 KB
    const uint32_t sbase = smem_u32(smem);

    const int tid  = threadIdx.x;
    const int lane = tid & 31;
    const int wid  = tid >> 5;
    const int wm   = wid & 1;
    const int wn   = wid >> 1;
    const int lrow = lane & 15;
    const int khf  = (lane >> 4) & 1;
    const int gid  = lane >> 2, tig = lane & 3;

    const int Moff = g_pairM[pidx];
    const int Noff = g_pairN[pidx];
    const bool diag = (Moff == Noff);

    // loader mapping: thread t -> row = t>>1, k-half = t&1 (32 f32 = 128 B)
    const int lrw  = tid >> 1;
    const int half = tid & 1;
    const size_t kbase = (size_t)seg * SEGD + (size_t)kq * KQ + half * 32;
    const float* __restrict__ srcA = F + (size_t)g_rowsrc[Moff + lrw] * FSTRIDE + kbase;
    const float* __restrict__ srcB = F + (size_t)g_rowsrc[Noff + lrw] * FSTRIDE + kbase;
    uint32_t stso[4];
#pragma unroll
    for (int j = 0; j < 4; j++)
        stso[j] = SW128((uint32_t)(lrw * 128 + half * 64 + j * 16));

    float4 v[8];
    auto ldg8 = [&](const float* s) {
        const float4* q4 = (const float4*)s;
#pragma unroll
        for (int q = 0; q < 8; q++) v[q] = q4[q];
    };
    auto sts4 = [&](uint32_t bufbase) {
#pragma unroll
        for (int j = 0; j < 4; j++)
            *(uint4*)(smem + (bufbase - sbase) + stso[j]) = cvt8(v[2 * j], v[2 * j + 1]);
    };

    float acc[2][4][4];
#pragma unroll
    for (int i = 0; i < 2; i++)
#pragma unroll
        for (int j = 0; j < 4; j++)
#pragma unroll
            for (int q = 0; q < 4; q++) acc[i][j][q] = 0.0f;

    auto compute = [&](int buf) {
        const uint32_t sa = sbase + buf * OP_BYTES;
        const uint32_t sb = diag ? sa : (sbase + (2 + buf) * OP_BYTES);
#pragma unroll
        for (int ks = 0; ks < 4; ks++) {
            const int kb = ks * 32 + khf * 16;
            uint32_t a[2][4], bf[2][4];
#pragma unroll
            for (int im = 0; im < 2; im++) {
                int row = wm * 32 + im * 16 + lrow;
                ldsm_x4(a[im][0], a[im][1], a[im][2], a[im][3],
                        sa + SW128(row * 128 + kb));
            }
#pragma unroll
            for (int j2 = 0; j2 < 2; j2++) {
                int row = wn * 32 + j2 * 16 + lrow;
                ldsm_x4(bf[j2][0], bf[j2][1], bf[j2][2], bf[j2][3],
                        sb + SW128(row * 128 + kb));
            }
#pragma unroll
            for (int im = 0; im < 2; im++)
#pragma unroll
                for (int jn = 0; jn < 4; jn++)
                    mma16816(acc[im][jn], a[im],
                             bf[jn >> 1][jn & 1], bf[jn >> 1][2 + (jn & 1)]);
        }
    };

    // prologue: stage chunk 0
    ldg8(srcA);
    sts4(sbase);
    if (!diag) { ldg8(srcB); sts4(sbase + 2 * OP_BYTES); }
    __syncthreads();

    for (int c = 0; c < CHPU; c++) {
        const bool more = (c + 1 < CHPU);
        if (more) ldg8(srcA + (size_t)(c + 1) * CK);   // DRAM latency hides under MMA
        compute(c & 1);
        if (more) {
            const uint32_t nb = sbase + ((c + 1) & 1) * OP_BYTES;
            sts4(nb);
            if (!diag) {                               // rare path; latency exposed, ok
                ldg8(srcB + (size_t)(c + 1) * CK);
                sts4(nb + 2 * OP_BYTES);
            }
        }
        __syncthreads();
    }

    float* Cb = g_gram + ((size_t)(seg * KSPLIT + kq) * MAXP + pidx) * (MT * MT);
#pragma unroll
    for (int im = 0; im < 2; im++) {
#pragma unroll
        for (int nb = 0; nb < 4; nb++) {
            const int r0 = wm * 32 + im * 16 + gid;
            const int c0 = wn * 32 + nb * 8 + tig * 2;
            *(float2*)&Cb[r0 * MT + c0] =
                make_float2(acc[im][nb][0] * TEMP_INV, acc[im][nb][1] * TEMP_INV);
            *(float2*)&Cb[(r0 + 8) * MT + c0] =
                make_float2(acc[im][nb][2] * TEMP_INV, acc[im][nb][3] * TEMP_INV);
        }
    }
}

// ---------------------------------------------------------------------------
// Loss over within-class pairs only (i < j, weight 2). Sums 8 K-partials,
// top-4-of-16 exp ratio; deterministic tree reduce; last block writes mean.
// ---------------------------------------------------------------------------
__global__ __launch_bounds__(256) void reduce_kernel(float* __restrict__ out) {
    const int t     = threadIdx.x;
    const int c     = blockIdx.x >> 6;
    const int local = ((blockIdx.x & 63) << 8) + t;
    const int i = local >> 7;
    const int j = local & 127;

    float loss = 0.0f;
    const int nc = g_cnum[c];
    if (i < j && j < nc) {
        const int T  = g_cT[c];
        const int ti = i >> 6, tj = j >> 6;
        const int pidx = g_cpbase[c] + ti * T - (ti * (ti - 1)) / 2 + (tj - ti);
        const int cell = (i & 63) * MT + (j & 63);

        float v[KSEG];
        float m = -1e30f;
#pragma unroll
        for (int k = 0; k < KSEG; k++) {
            float s = 0.0f;
#pragma unroll
            for (int kq = 0; kq < KSPLIT; kq++)
                s += g_gram[((size_t)(k * KSPLIT + kq) * MAXP + pidx) * (MT * MT) + cell];
            v[k] = s;
            m = fmaxf(m, s);
        }
        float tot = 0.0f, t0 = 0.0f, t1 = 0.0f, t2 = 0.0f, t3 = 0.0f;
#pragma unroll
        for (int k = 0; k < KSEG; k++) {
            const float e = __expf(v[k] - m);
            tot += e;
            if (e > t0)      { t3 = t2; t2 = t1; t1 = t0; t0 = e; }
            else if (e > t1) { t3 = t2; t2 = t1; t1 = e; }
            else if (e > t2) { t3 = t2; t2 = e; }
            else if (e > t3) { t3 = e; }
        }
        loss = -2.0f * __logf((t0 + t1 + t2 + t3) / tot);   // both (a,b),(b,a)
    }

    __shared__ float red[256];
    red[t] = loss;
    __syncthreads();
#pragma unroll
    for (int s = 128; s > 0; s >>= 1) {
        if (t < s) red[t] += red[t + s];
        __syncthreads();
    }

    __shared__ int isLast;
    if (t == 0) {
        g_partials[blockIdx.x] = red[0];
        __threadfence();
        int cn = atomicAdd(&g_red_count, 1);
        isLast = (cn == gridDim.x - 1);
    }
    __syncthreads();

    if (isLast) {
        float s = __ldcg(&g_partials[t]) + __ldcg(&g_partials[t + 256]);
        if (t + 512 < 640) s += __ldcg(&g_partials[t + 512]);
        red[t] = s;
        __syncthreads();
#pragma unroll
        for (int sh = 128; sh > 0; sh >>= 1) {
            if (t < sh) red[t] += red[t + sh];
            __syncthreads();
        }
        if (t == 0) {
            out[0] = red[0] / (float)(NS * NS);
            g_red_count = 0;           // reset for graph replay
        }
    }
}

// ---------------------------------------------------------------------------
extern "C" void kernel_launch(void* const* d_in, const int* in_sizes, int n_in,
                              void* d_out, int out_size) {
    const float* features = (const float*)d_in[0];
    const int*   labels   = (const int*)d_in[1];
    (void)in_sizes; (void)n_in; (void)out_size;

    prep_kernel<<<1, NS>>>(labels);
    dim3 grid(MAXP, KSEG, KSPLIT);     // inactive pairs exit on g_P
    gemm_kernel<<<grid, 128>>>(features);
    reduce_kernel<<<NCLASS * 64, 256>>>((float*)d_out);
}